// round 2
// baseline (speedup 1.0000x reference)
#include <cuda_runtime.h>
#include <cuda_bf16.h>

#define BB 8
#define CC 64
#define CQ 8
#define NN 4096
#define NT 64          // key tile size
#define SC 16          // scores-in-registers sub-chunk

// Scratch for projected Q, K, V (device globals: allocation-free rule)
__device__ float g_Q[BB * NN * CQ];   // [b][n][cq]  (1 MB)
__device__ float g_K[BB * NN * CQ];   // [b][n][cq]  (1 MB)
__device__ float g_V[BB * NN * CC];   // [b][n][c]   (8 MB)

// ---------------------------------------------------------------------------
// Kernel 1: 1x1-conv projections (per-pixel linear over channels)
// grid (N/256, B), 256 threads. Each thread = one pixel.
// ---------------------------------------------------------------------------
__global__ void __launch_bounds__(256, 1) proj_kernel(
    const float* __restrict__ x,
    const float* __restrict__ wq, const float* __restrict__ bq,
    const float* __restrict__ wk, const float* __restrict__ bk,
    const float* __restrict__ wv, const float* __restrict__ bv)
{
    __shared__ float wvT[CC * CC];   // wvT[c'][c] = wv[c][c']  (16 KB)
    __shared__ float wqT[CC * CQ];
    __shared__ float wkT[CC * CQ];
    __shared__ float s_bv[CC];
    __shared__ float s_bq[CQ];
    __shared__ float s_bk[CQ];

    const int tid = threadIdx.x;
    const int b   = blockIdx.y;
    const int n   = blockIdx.x * 256 + tid;

    for (int idx = tid; idx < CC * CC; idx += 256) {
        int c = idx >> 6, cp = idx & 63;
        wvT[cp * CC + c] = wv[idx];
    }
    for (int idx = tid; idx < CQ * CC; idx += 256) {
        int cq = idx >> 6, cp = idx & 63;
        wqT[cp * CQ + cq] = wq[idx];
        wkT[cp * CQ + cq] = wk[idx];
    }
    if (tid < CC) s_bv[tid] = bv[tid];
    if (tid < CQ) { s_bq[tid] = bq[tid]; s_bk[tid] = bk[tid]; }
    __syncthreads();

    const float* xb = x + (size_t)b * CC * NN + n;

    float4 accv[CC / 4];
    float accq[CQ], acck[CQ];
    #pragma unroll
    for (int c4 = 0; c4 < CC / 4; ++c4) {
        accv[c4].x = s_bv[c4 * 4 + 0];
        accv[c4].y = s_bv[c4 * 4 + 1];
        accv[c4].z = s_bv[c4 * 4 + 2];
        accv[c4].w = s_bv[c4 * 4 + 3];
    }
    #pragma unroll
    for (int cq = 0; cq < CQ; ++cq) { accq[cq] = s_bq[cq]; acck[cq] = s_bk[cq]; }

    #pragma unroll 2
    for (int cp = 0; cp < CC; ++cp) {
        const float xv = xb[(size_t)cp * NN];             // coalesced LDG
        const float4* wrow = (const float4*)&wvT[cp * CC];
        #pragma unroll
        for (int c4 = 0; c4 < CC / 4; ++c4) {
            float4 w = wrow[c4];                           // broadcast LDS.128
            accv[c4].x += w.x * xv;
            accv[c4].y += w.y * xv;
            accv[c4].z += w.z * xv;
            accv[c4].w += w.w * xv;
        }
        #pragma unroll
        for (int cq = 0; cq < CQ; ++cq) {
            accq[cq] += wqT[cp * CQ + cq] * xv;
            acck[cq] += wkT[cp * CQ + cq] * xv;
        }
    }

    float4* Qo = (float4*)(g_Q + ((size_t)b * NN + n) * CQ);
    float4* Ko = (float4*)(g_K + ((size_t)b * NN + n) * CQ);
    Qo[0] = make_float4(accq[0], accq[1], accq[2], accq[3]);
    Qo[1] = make_float4(accq[4], accq[5], accq[6], accq[7]);
    Ko[0] = make_float4(acck[0], acck[1], acck[2], acck[3]);
    Ko[1] = make_float4(acck[4], acck[5], acck[6], acck[7]);

    float4* Vo = (float4*)(g_V + ((size_t)b * NN + n) * CC);
    #pragma unroll
    for (int c4 = 0; c4 < CC / 4; ++c4) Vo[c4] = accv[c4];
}

// ---------------------------------------------------------------------------
// Kernel 2: fused flash attention, register-resident scores (no S smem tile).
// Block = 128 threads = 64 queries x 2 channel-halves (32 ch per thread).
// grid (N/64, B) = (64, 8) = 512 blocks. 4 CTAs/SM -> 16 warps/SM.
// smem: K tile (2 KB) + V tile (16 KB) = 18 KB static.
// ---------------------------------------------------------------------------
__global__ void __launch_bounds__(128, 4) attn_kernel(float* __restrict__ out)
{
    __shared__ __align__(16) float4 Ks[NT * 2];    // [64 keys][2 float4]
    __shared__ __align__(16) float4 Vs[NT * 16];   // [64 keys][16 float4]

    const int tid  = threadIdx.x;
    const int half = tid >> 6;       // channel half: 0 or 1
    const int qi   = tid & 63;       // query within block
    const int b    = blockIdx.y;
    const int i    = blockIdx.x * 64 + qi;

    const float4* Qp = (const float4*)(g_Q + ((size_t)b * NN + i) * CQ);
    const float4 q0 = Qp[0];
    const float4 q1 = Qp[1];

    const float4* Kg4 = (const float4*)(g_K + (size_t)b * NN * CQ);
    const float4* Vg4 = (const float4*)(g_V + (size_t)b * NN * CC);

    float4 o[8];
    #pragma unroll
    for (int c4 = 0; c4 < 8; ++c4) o[c4] = make_float4(0.f, 0.f, 0.f, 0.f);
    float m = -1e30f;
    float l = 0.f;

    #pragma unroll 1
    for (int t = 0; t < NN / NT; ++t) {
        __syncthreads();
        Ks[tid] = Kg4[t * 128 + tid];
        #pragma unroll
        for (int r = 0; r < 8; ++r) Vs[r * 128 + tid] = Vg4[t * 1024 + r * 128 + tid];
        __syncthreads();

        #pragma unroll 1
        for (int sc = 0; sc < NT / SC; ++sc) {
            // --- scores for this 16-key sub-chunk (registers) ---
            float s[SC];
            float cmax = -1e30f;
            #pragma unroll
            for (int jj = 0; jj < SC; ++jj) {
                const int j = sc * SC + jj;
                const float4 k0 = Ks[j * 2 + 0];          // broadcast LDS
                const float4 k1 = Ks[j * 2 + 1];
                const float v = q0.x * k0.x + q0.y * k0.y + q0.z * k0.z + q0.w * k0.w
                              + q1.x * k1.x + q1.y * k1.y + q1.z * k1.z + q1.w * k1.w;
                s[jj] = v;
                cmax = fmaxf(cmax, v);
            }

            // --- online softmax rescale (thread-private state) ---
            const float newm  = fmaxf(m, cmax);
            const float scale = __expf(m - newm);
            m = newm;
            l *= scale;
            #pragma unroll
            for (int c4 = 0; c4 < 8; ++c4) {
                o[c4].x *= scale; o[c4].y *= scale; o[c4].z *= scale; o[c4].w *= scale;
            }

            // --- P @ V accumulate over this thread's 32 channels ---
            #pragma unroll
            for (int jj = 0; jj < SC; ++jj) {
                const float p = __expf(s[jj] - m);
                l += p;
                const float4* vrow = &Vs[(sc * SC + jj) * 16 + half * 8];
                #pragma unroll
                for (int c4 = 0; c4 < 8; ++c4) {
                    const float4 v = vrow[c4];            // warp-uniform broadcast
                    o[c4].x += p * v.x;
                    o[c4].y += p * v.y;
                    o[c4].z += p * v.z;
                    o[c4].w += p * v.w;
                }
            }
        }
    }

    const float inv = 1.0f / l;
    float* op = out + (size_t)b * CC * NN + (size_t)(half * 32) * NN + i;
    #pragma unroll
    for (int c4 = 0; c4 < 8; ++c4) {
        op[(size_t)(c4 * 4 + 0) * NN] = o[c4].x * inv;
        op[(size_t)(c4 * 4 + 1) * NN] = o[c4].y * inv;
        op[(size_t)(c4 * 4 + 2) * NN] = o[c4].z * inv;
        op[(size_t)(c4 * 4 + 3) * NN] = o[c4].w * inv;
    }
}

// ---------------------------------------------------------------------------
extern "C" void kernel_launch(void* const* d_in, const int* in_sizes, int n_in,
                              void* d_out, int out_size)
{
    const float* x  = (const float*)d_in[0];
    const float* wq = (const float*)d_in[1];
    const float* bq = (const float*)d_in[2];
    const float* wk = (const float*)d_in[3];
    const float* bk = (const float*)d_in[4];
    const float* wv = (const float*)d_in[5];
    const float* bv = (const float*)d_in[6];
    float* out = (float*)d_out;

    dim3 pgrid(NN / 256, BB);
    proj_kernel<<<pgrid, 256>>>(x, wq, bq, wk, bk, wv, bv);

    dim3 agrid(NN / 64, BB);
    attn_kernel<<<agrid, 128>>>(out);
}

// round 4
// speedup vs baseline: 5.7384x; 5.7384x over previous
#include <cuda_runtime.h>
#include <cuda_bf16.h>
#include <cstdint>

#define BB 8
#define CC 64
#define CQ 8
#define NN 4096
#define KT 64              // keys per tile
#define QB 128             // queries per block
#define NTILES (NN / KT)

// Device scratch (allocation-free rule)
__device__ float g_Q[BB * NN * CQ];            // [b][n][cq] f32
__device__ float g_K[BB * NN * CQ];            // [b][n][cq] f32
__device__ __nv_bfloat16 g_Vb[BB * CC * NN];   // [b][c][n]  bf16 (V^T layout)

// ---------------------------------------------------------------------------
// mma.sync m16n8k16 bf16 (baseline PTX, sm_80+; runs on tensor pipe)
// ---------------------------------------------------------------------------
#define MMA16816(d, a0, a1, a2, a3, b0, b1) \
    asm volatile("mma.sync.aligned.m16n8k16.row.col.f32.bf16.bf16.f32 " \
        "{%0,%1,%2,%3}, {%4,%5,%6,%7}, {%8,%9}, {%0,%1,%2,%3};" \
        : "+f"((d)[0]), "+f"((d)[1]), "+f"((d)[2]), "+f"((d)[3]) \
        : "r"(a0), "r"(a1), "r"(a2), "r"(a3), "r"(b0), "r"(b1))

__device__ __forceinline__ uint32_t packbf(float lo, float hi) {
    uint32_t r;
    asm("cvt.rn.bf16x2.f32 %0, %1, %2;" : "=r"(r) : "f"(hi), "f"(lo));
    return r;
}

__device__ __forceinline__ float dot8(const float4 qa, const float4 qb,
                                      const float4 ka, const float4 kb) {
    return qa.x * ka.x + qa.y * ka.y + qa.z * ka.z + qa.w * ka.w
         + qb.x * kb.x + qb.y * kb.y + qb.z * kb.z + qb.w * kb.w;
}

// ---------------------------------------------------------------------------
// Kernel 1: 1x1-conv projections. Q,K f32 [b][n][cq]; V bf16 [b][c][n].
// ---------------------------------------------------------------------------
__global__ void __launch_bounds__(256, 1) proj_kernel(
    const float* __restrict__ x,
    const float* __restrict__ wq, const float* __restrict__ bq,
    const float* __restrict__ wk, const float* __restrict__ bk,
    const float* __restrict__ wv, const float* __restrict__ bv)
{
    __shared__ float wvT[CC * CC];
    __shared__ float wqT[CC * CQ];
    __shared__ float wkT[CC * CQ];
    __shared__ float s_bv[CC];
    __shared__ float s_bq[CQ];
    __shared__ float s_bk[CQ];

    const int tid = threadIdx.x;
    const int b   = blockIdx.y;
    const int n   = blockIdx.x * 256 + tid;

    for (int idx = tid; idx < CC * CC; idx += 256) {
        int c = idx >> 6, cp = idx & 63;
        wvT[cp * CC + c] = wv[idx];
    }
    for (int idx = tid; idx < CQ * CC; idx += 256) {
        int cq = idx >> 6, cp = idx & 63;
        wqT[cp * CQ + cq] = wq[idx];
        wkT[cp * CQ + cq] = wk[idx];
    }
    if (tid < CC) s_bv[tid] = bv[tid];
    if (tid < CQ) { s_bq[tid] = bq[tid]; s_bk[tid] = bk[tid]; }
    __syncthreads();

    const float* xb = x + (size_t)b * CC * NN + n;

    float4 accv[CC / 4];
    float accq[CQ], acck[CQ];
    #pragma unroll
    for (int c4 = 0; c4 < CC / 4; ++c4) {
        accv[c4].x = s_bv[c4 * 4 + 0];
        accv[c4].y = s_bv[c4 * 4 + 1];
        accv[c4].z = s_bv[c4 * 4 + 2];
        accv[c4].w = s_bv[c4 * 4 + 3];
    }
    #pragma unroll
    for (int cq = 0; cq < CQ; ++cq) { accq[cq] = s_bq[cq]; acck[cq] = s_bk[cq]; }

    #pragma unroll 2
    for (int cp = 0; cp < CC; ++cp) {
        const float xv = xb[(size_t)cp * NN];
        const float4* wrow = (const float4*)&wvT[cp * CC];
        #pragma unroll
        for (int c4 = 0; c4 < CC / 4; ++c4) {
            float4 w = wrow[c4];
            accv[c4].x += w.x * xv;
            accv[c4].y += w.y * xv;
            accv[c4].z += w.z * xv;
            accv[c4].w += w.w * xv;
        }
        #pragma unroll
        for (int cq = 0; cq < CQ; ++cq) {
            accq[cq] += wqT[cp * CQ + cq] * xv;
            acck[cq] += wkT[cp * CQ + cq] * xv;
        }
    }

    float4* Qo = (float4*)(g_Q + ((size_t)b * NN + n) * CQ);
    float4* Ko = (float4*)(g_K + ((size_t)b * NN + n) * CQ);
    Qo[0] = make_float4(accq[0], accq[1], accq[2], accq[3]);
    Qo[1] = make_float4(accq[4], accq[5], accq[6], accq[7]);
    Ko[0] = make_float4(acck[0], acck[1], acck[2], acck[3]);
    Ko[1] = make_float4(acck[4], acck[5], acck[6], acck[7]);

    __nv_bfloat16* Vo = g_Vb + (size_t)b * CC * NN + n;
    #pragma unroll
    for (int c4 = 0; c4 < CC / 4; ++c4) {
        Vo[(size_t)(c4 * 4 + 0) * NN] = __float2bfloat16(accv[c4].x);
        Vo[(size_t)(c4 * 4 + 1) * NN] = __float2bfloat16(accv[c4].y);
        Vo[(size_t)(c4 * 4 + 2) * NN] = __float2bfloat16(accv[c4].z);
        Vo[(size_t)(c4 * 4 + 3) * NN] = __float2bfloat16(accv[c4].w);
    }
}

// ---------------------------------------------------------------------------
// Kernel 2: fused attention; scores+exp fp32 on CUDA cores in mma-fragment
// layout, P.V on tensor pipe via mma.sync bf16. P never touches smem.
// Block = 128 thr = 4 warps; warp = 32 query rows. grid (32, 8).
// smem: K tile 3KB (stride-48B rows) + V^T tile 8KB (xor-swizzled) = 11KB.
// ---------------------------------------------------------------------------
__global__ void __launch_bounds__(128, 2) attn_kernel(float* __restrict__ out)
{
    __shared__ __align__(16) float smK[KT * 12];   // key j at smK + j*12 (48B stride)
    __shared__ __align__(16) char  smV[CC * 128];  // V^T[c][j] bf16, 128B rows, swizzled

    const int tid  = threadIdx.x;
    const int w    = tid >> 5;
    const int lane = tid & 31;
    const int g    = lane >> 2;      // fragment row group
    const int t4   = lane & 3;       // fragment quad index
    const int b    = blockIdx.y;
    const int iw   = blockIdx.x * QB + w * 32 + g;

    // Persistent Q rows: g, g+8, g+16, g+24 within this warp's 32 queries
    const float4* Qb = (const float4*)(g_Q + (size_t)b * NN * CQ);
    float4 q[4][2];
    #pragma unroll
    for (int r = 0; r < 4; ++r) {
        q[r][0] = Qb[(iw + r * 8) * 2 + 0];
        q[r][1] = Qb[(iw + r * 8) * 2 + 1];
    }

    const float4* Kg4 = (const float4*)(g_K + (size_t)b * NN * CQ);
    const __nv_bfloat16* Vg = g_Vb + (size_t)b * CC * NN;

    float acc[2][8][4];
    #pragma unroll
    for (int m = 0; m < 2; ++m)
        #pragma unroll
        for (int nb = 0; nb < 8; ++nb)
            #pragma unroll
            for (int e = 0; e < 4; ++e) acc[m][nb][e] = 0.f;
    float lsum[4] = {0.f, 0.f, 0.f, 0.f};

    // Staging maps
    const int kj = tid >> 1, kh = tid & 1;             // K: thread -> (key, half)
    float* kdst = smK + kj * 12 + kh * 4;
    int vrow[4], vc16[4];
    char* vdst[4];
    #pragma unroll
    for (int r = 0; r < 4; ++r) {
        const int idx = r * 128 + tid;
        vrow[r] = idx >> 3;
        vc16[r] = idx & 7;
        vdst[r] = smV + vrow[r] * 128 + ((vc16[r] ^ (vrow[r] & 7)) << 4);
    }

    // Prefetch tile 0
    float4 kreg = Kg4[tid];
    float4 vreg[4];
    #pragma unroll
    for (int r = 0; r < 4; ++r)
        vreg[r] = *(const float4*)(Vg + (size_t)vrow[r] * NN + vc16[r] * 8);

    #pragma unroll 1
    for (int t = 0; t < NTILES; ++t) {
        __syncthreads();                               // prior compute done
        *(float4*)kdst = kreg;
        #pragma unroll
        for (int r = 0; r < 4; ++r) *(float4*)vdst[r] = vreg[r];

        const int tn = (t + 1 < NTILES) ? t + 1 : t;   // prefetch next tile
        kreg = Kg4[tn * 128 + tid];
        #pragma unroll
        for (int r = 0; r < 4; ++r)
            vreg[r] = *(const float4*)(Vg + (size_t)vrow[r] * NN + tn * KT + vc16[r] * 8);
        __syncthreads();                               // tiles visible

        #pragma unroll
        for (int kt = 0; kt < 4; ++kt) {
            const int j0 = kt * 16 + 2 * t4;
            const float* kp = smK + j0 * 12;
            // keys j0, j0+1, j0+8, j0+9 (8 floats each)
            const float4 kA0 = *(const float4*)(kp);
            const float4 kA1 = *(const float4*)(kp + 4);
            const float4 kB0 = *(const float4*)(kp + 12);
            const float4 kB1 = *(const float4*)(kp + 16);
            const float4 kC0 = *(const float4*)(kp + 96);
            const float4 kC1 = *(const float4*)(kp + 100);
            const float4 kD0 = *(const float4*)(kp + 108);
            const float4 kD1 = *(const float4*)(kp + 112);

            float p[4][4];
            #pragma unroll
            for (int r = 0; r < 4; ++r) {
                p[r][0] = __expf(dot8(q[r][0], q[r][1], kA0, kA1));
                p[r][1] = __expf(dot8(q[r][0], q[r][1], kB0, kB1));
                p[r][2] = __expf(dot8(q[r][0], q[r][1], kC0, kC1));
                p[r][3] = __expf(dot8(q[r][0], q[r][1], kD0, kD1));
                lsum[r] += (p[r][0] + p[r][1]) + (p[r][2] + p[r][3]);
            }

            uint32_t a[2][4];
            #pragma unroll
            for (int m = 0; m < 2; ++m) {
                a[m][0] = packbf(p[2 * m][0],     p[2 * m][1]);
                a[m][1] = packbf(p[2 * m + 1][0], p[2 * m + 1][1]);
                a[m][2] = packbf(p[2 * m][2],     p[2 * m][3]);
                a[m][3] = packbf(p[2 * m + 1][2], p[2 * m + 1][3]);
            }

            const uint32_t ch0 = ((uint32_t)((2 * kt) ^ g) << 4) + (t4 << 2);
            const uint32_t ch1 = ((uint32_t)((2 * kt + 1) ^ g) << 4) + (t4 << 2);
            #pragma unroll
            for (int nb = 0; nb < 8; ++nb) {
                const char* rp = smV + (nb * 8 + g) * 128;
                const uint32_t b0 = *(const uint32_t*)(rp + ch0);
                const uint32_t b1 = *(const uint32_t*)(rp + ch1);
                MMA16816(acc[0][nb], a[0][0], a[0][1], a[0][2], a[0][3], b0, b1);
                MMA16816(acc[1][nb], a[1][0], a[1][1], a[1][2], a[1][3], b0, b1);
            }
        }
    }

    // Reduce l across the 4 lanes sharing each row (quad t4)
    #pragma unroll
    for (int r = 0; r < 4; ++r) {
        lsum[r] += __shfl_xor_sync(0xFFFFFFFFu, lsum[r], 1);
        lsum[r] += __shfl_xor_sync(0xFFFFFFFFu, lsum[r], 2);
    }
    const float inv[4] = {1.f / lsum[0], 1.f / lsum[1], 1.f / lsum[2], 1.f / lsum[3]};

    float* outb = out + (size_t)b * CC * NN;
    const int ibase = blockIdx.x * QB + w * 32;
    #pragma unroll
    for (int m = 0; m < 2; ++m) {
        const int rA = ibase + m * 16 + g;       // rows for c0,c1
        const int rB = rA + 8;                   // rows for c2,c3
        const float ivA = inv[m * 2 + 0];
        const float ivB = inv[m * 2 + 1];
        #pragma unroll
        for (int nb = 0; nb < 8; ++nb) {
            const int c = nb * 8 + 2 * t4;
            outb[(size_t)c * NN + rA]       = acc[m][nb][0] * ivA;
            outb[(size_t)(c + 1) * NN + rA] = acc[m][nb][1] * ivA;
            outb[(size_t)c * NN + rB]       = acc[m][nb][2] * ivB;
            outb[(size_t)(c + 1) * NN + rB] = acc[m][nb][3] * ivB;
        }
    }
}

// ---------------------------------------------------------------------------
extern "C" void kernel_launch(void* const* d_in, const int* in_sizes, int n_in,
                              void* d_out, int out_size)
{
    const float* x  = (const float*)d_in[0];
    const float* wq = (const float*)d_in[1];
    const float* bq = (const float*)d_in[2];
    const float* wk = (const float*)d_in[3];
    const float* bk = (const float*)d_in[4];
    const float* wv = (const float*)d_in[5];
    const float* bv = (const float*)d_in[6];
    float* out = (float*)d_out;

    dim3 pgrid(NN / 256, BB);
    proj_kernel<<<pgrid, 256>>>(x, wq, bq, wk, bk, wv, bv);

    dim3 agrid(NN / QB, BB);
    attn_kernel<<<agrid, 128>>>(out);
}

// round 5
// speedup vs baseline: 7.1653x; 1.2487x over previous
#include <cuda_runtime.h>
#include <cuda_bf16.h>
#include <cstdint>

#define BB 8
#define CC 64
#define CQ 8
#define NN 4096
#define KT 64
#define NTILES (NN / KT)
#define LOG2E 1.4426950408889634f

// Device scratch (allocation-free rule)
__device__ float g_Q[BB * NN * CQ];            // [b][n][cq] f32, pre-scaled by log2e
__device__ uint4 g_Khi[BB * NN];               // [b][n]: 8 bf16 (hi split)
__device__ uint4 g_Klo[BB * NN];               // [b][n]: 8 bf16 (lo split)
__device__ __nv_bfloat16 g_Vb[BB * CC * NN];   // [b][c][n] bf16 (V^T)

// ---------------------------------------------------------------------------
// PTX helpers (all baseline compute_103-safe: sm_75/80-era instructions)
// ---------------------------------------------------------------------------
__device__ __forceinline__ uint32_t smem_u32(const void* p) {
    uint32_t a;
    asm("{ .reg .u64 t; cvta.to.shared.u64 t, %1; cvt.u32.u64 %0, t; }" : "=r"(a) : "l"(p));
    return a;
}
// pack two f32 -> bf16x2 (lo in low half, hi in high half)
__device__ __forceinline__ uint32_t packbf(float lo, float hi) {
    uint32_t r;
    asm("cvt.rn.bf16x2.f32 %0, %1, %2;" : "=r"(r) : "f"(hi), "f"(lo));
    return r;
}
__device__ __forceinline__ float ex2f(float x) {
    float y;
    asm("ex2.approx.f32 %0, %1;" : "=f"(y) : "f"(x));
    return y;
}
#define LDSM4(r0, r1, r2, r3, a) \
    asm volatile("ldmatrix.sync.aligned.m8n8.x4.shared.b16 {%0,%1,%2,%3}, [%4];" \
        : "=r"(r0), "=r"(r1), "=r"(r2), "=r"(r3) : "r"(a))

// m16n8k8 bf16 MMA, C = 0 (fresh accumulate)
#define MMA1688_Z(d, a0, a1, b0) \
    asm volatile("mma.sync.aligned.m16n8k8.row.col.f32.bf16.bf16.f32 " \
        "{%0,%1,%2,%3}, {%4,%5}, {%6}, {%7,%7,%7,%7};" \
        : "=f"((d)[0]), "=f"((d)[1]), "=f"((d)[2]), "=f"((d)[3]) \
        : "r"(a0), "r"(a1), "r"(b0), "f"(0.f))
// m16n8k8 bf16 MMA, accumulate in place
#define MMA1688(d, a0, a1, b0) \
    asm volatile("mma.sync.aligned.m16n8k8.row.col.f32.bf16.bf16.f32 " \
        "{%0,%1,%2,%3}, {%4,%5}, {%6}, {%0,%1,%2,%3};" \
        : "+f"((d)[0]), "+f"((d)[1]), "+f"((d)[2]), "+f"((d)[3]) \
        : "r"(a0), "r"(a1), "r"(b0))
// m16n8k16 bf16 MMA, accumulate in place
#define MMA16816(d, a0, a1, a2, a3, b0, b1) \
    asm volatile("mma.sync.aligned.m16n8k16.row.col.f32.bf16.bf16.f32 " \
        "{%0,%1,%2,%3}, {%4,%5,%6,%7}, {%8,%9}, {%0,%1,%2,%3};" \
        : "+f"((d)[0]), "+f"((d)[1]), "+f"((d)[2]), "+f"((d)[3]) \
        : "r"(a0), "r"(a1), "r"(a2), "r"(a3), "r"(b0), "r"(b1))

// ---------------------------------------------------------------------------
// Kernel 1: 1x1-conv projections.
//   Q f32 (scaled by log2e), K split into bf16 hi/lo, V^T bf16.
// 128-thr blocks, 4 CTAs/SM for latency hiding.
// ---------------------------------------------------------------------------
__global__ void __launch_bounds__(128, 4) proj_kernel(
    const float* __restrict__ x,
    const float* __restrict__ wq, const float* __restrict__ bq,
    const float* __restrict__ wk, const float* __restrict__ bk,
    const float* __restrict__ wv, const float* __restrict__ bv)
{
    __shared__ float wvT[CC * CC];
    __shared__ float wqT[CC * CQ];
    __shared__ float wkT[CC * CQ];
    __shared__ float s_bv[CC];
    __shared__ float s_bq[CQ];
    __shared__ float s_bk[CQ];

    const int tid = threadIdx.x;
    const int b   = blockIdx.y;
    const int n   = blockIdx.x * 128 + tid;

    for (int idx = tid; idx < CC * CC; idx += 128) {
        int c = idx >> 6, cp = idx & 63;
        wvT[cp * CC + c] = wv[idx];
    }
    for (int idx = tid; idx < CQ * CC; idx += 128) {
        int cq = idx >> 6, cp = idx & 63;
        wqT[cp * CQ + cq] = wq[idx];
        wkT[cp * CQ + cq] = wk[idx];
    }
    if (tid < CC) s_bv[tid] = bv[tid];
    if (tid < CQ) { s_bq[tid] = bq[tid]; s_bk[tid] = bk[tid]; }
    __syncthreads();

    const float* xb = x + (size_t)b * CC * NN + n;

    float4 accv[CC / 4];
    float accq[CQ], acck[CQ];
    #pragma unroll
    for (int c4 = 0; c4 < CC / 4; ++c4) {
        accv[c4].x = s_bv[c4 * 4 + 0];
        accv[c4].y = s_bv[c4 * 4 + 1];
        accv[c4].z = s_bv[c4 * 4 + 2];
        accv[c4].w = s_bv[c4 * 4 + 3];
    }
    #pragma unroll
    for (int cq = 0; cq < CQ; ++cq) { accq[cq] = s_bq[cq]; acck[cq] = s_bk[cq]; }

    #pragma unroll 4
    for (int cp = 0; cp < CC; ++cp) {
        const float xv = xb[(size_t)cp * NN];
        const float4* wrow = (const float4*)&wvT[cp * CC];
        #pragma unroll
        for (int c4 = 0; c4 < CC / 4; ++c4) {
            float4 w = wrow[c4];
            accv[c4].x += w.x * xv;
            accv[c4].y += w.y * xv;
            accv[c4].z += w.z * xv;
            accv[c4].w += w.w * xv;
        }
        #pragma unroll
        for (int cq = 0; cq < CQ; ++cq) {
            accq[cq] += wqT[cp * CQ + cq] * xv;
            acck[cq] += wkT[cp * CQ + cq] * xv;
        }
    }

    // Q: f32 scaled by log2e (so exp(s) == exp2(q'.k))
    float4* Qo = (float4*)(g_Q + ((size_t)b * NN + n) * CQ);
    Qo[0] = make_float4(accq[0] * LOG2E, accq[1] * LOG2E, accq[2] * LOG2E, accq[3] * LOG2E);
    Qo[1] = make_float4(accq[4] * LOG2E, accq[5] * LOG2E, accq[6] * LOG2E, accq[7] * LOG2E);

    // K: bf16 hi/lo split, 8 channels packed into uint4 each
    uint32_t hiw[4], low[4];
    #pragma unroll
    for (int p = 0; p < 4; ++p) {
        const float k0 = acck[2 * p], k1 = acck[2 * p + 1];
        const uint32_t h = packbf(k0, k1);
        const float h0 = __uint_as_float(h << 16);
        const float h1 = __uint_as_float(h & 0xFFFF0000u);
        hiw[p] = h;
        low[p] = packbf(k0 - h0, k1 - h1);
    }
    g_Khi[(size_t)b * NN + n] = make_uint4(hiw[0], hiw[1], hiw[2], hiw[3]);
    g_Klo[(size_t)b * NN + n] = make_uint4(low[0], low[1], low[2], low[3]);

    // V^T bf16: [b][c][n]
    __nv_bfloat16* Vo = g_Vb + (size_t)b * CC * NN + n;
    #pragma unroll
    for (int c4 = 0; c4 < CC / 4; ++c4) {
        Vo[(size_t)(c4 * 4 + 0) * NN] = __float2bfloat16(accv[c4].x);
        Vo[(size_t)(c4 * 4 + 1) * NN] = __float2bfloat16(accv[c4].y);
        Vo[(size_t)(c4 * 4 + 2) * NN] = __float2bfloat16(accv[c4].z);
        Vo[(size_t)(c4 * 4 + 3) * NN] = __float2bfloat16(accv[c4].w);
    }
}

// ---------------------------------------------------------------------------
// Kernel 2: fully tensorized fused attention.
//   scores: mma.m16n8k8 with bf16 hi/lo split of Q and K (fp32-exact to ~2^-17)
//   exp:    single ex2.approx (log2e pre-folded into Q)
//   P.V:    mma.m16n8k16 bf16; l via ones-column MMA
// Block = 128 thr = 4 warps x 16 query rows. grid (64, 8) = 512 blocks.
// smem: Khi 1KB + Klo 1KB + V^T 8KB = 10KB -> 3 CTAs/SM (reg-capped).
// ---------------------------------------------------------------------------
__global__ void __launch_bounds__(128, 3) attn_kernel(float* __restrict__ out)
{
    __shared__ __align__(16) uint4 smKhi[KT];     // [key]: 8 bf16 chans (16B row)
    __shared__ __align__(16) uint4 smKlo[KT];
    __shared__ __align__(16) char  smV[CC * 128]; // V^T[c][j] bf16, xor-swizzled

    const int tid  = threadIdx.x;
    const int w    = tid >> 5;
    const int lane = tid & 31;
    const int g    = lane >> 2;
    const int t4   = lane & 3;
    const int b    = blockIdx.y;
    const int ibase = blockIdx.x * 64 + w * 16;

    // --- Q fragments (rows g, g+8; chans 2t4, 2t4+1), hi/lo bf16 split ---
    const float* Qb = g_Q + (size_t)b * NN * CQ;
    uint32_t qhi[2], qlo[2];
    #pragma unroll
    for (int r = 0; r < 2; ++r) {
        const float* qp = Qb + (size_t)(ibase + g + r * 8) * CQ + 2 * t4;
        const float q0 = qp[0], q1 = qp[1];
        const uint32_t h = packbf(q0, q1);
        qhi[r] = h;
        qlo[r] = packbf(q0 - __uint_as_float(h << 16),
                        q1 - __uint_as_float(h & 0xFFFF0000u));
    }

    const __nv_bfloat16* Vg = g_Vb + (size_t)b * CC * NN;
    const uint4* Ksrc = ((tid < 64) ? g_Khi : g_Klo) + (size_t)b * NN;
    const int kidx = tid & 63;
    uint4* kdst = ((tid < 64) ? smKhi : smKlo) + kidx;

    // V staging map (identical to proven round-4 layout)
    int vrow[4], vc16[4];
    char* vdst[4];
    #pragma unroll
    for (int r = 0; r < 4; ++r) {
        const int idx = r * 128 + tid;
        vrow[r] = idx >> 3;
        vc16[r] = idx & 7;
        vdst[r] = smV + vrow[r] * 128 + ((vc16[r] ^ (vrow[r] & 7)) << 4);
    }

    // ldmatrix source addresses
    const uint32_t aKhi = smem_u32(smKhi) + lane * 16;   // rows 0-31; +512 rows 32-63
    const uint32_t aKlo = smem_u32(smKlo) + lane * 16;
    const int mat = lane >> 3, mrow = lane & 7, m01 = mat & 1;
    uint32_t vbase[4];
    int vxor[4];
    #pragma unroll
    for (int c = 0; c < 4; ++c) {
        const int row = (2 * c + (mat >> 1)) * 8 + mrow;
        vbase[c] = smem_u32(smV) + row * 128;
        vxor[c]  = row & 7;
    }

    // Prefetch tile 0
    uint4 kreg = Ksrc[kidx];
    float4 vreg[4];
    #pragma unroll
    for (int r = 0; r < 4; ++r)
        vreg[r] = *(const float4*)(Vg + (size_t)vrow[r] * NN + vc16[r] * 8);

    float acc[8][4];
    #pragma unroll
    for (int nb = 0; nb < 8; ++nb)
        #pragma unroll
        for (int e = 0; e < 4; ++e) acc[nb][e] = 0.f;
    float lacc[4] = {0.f, 0.f, 0.f, 0.f};
    const uint32_t ONES = 0x3F803F80u;   // bf16 {1.0, 1.0}

    #pragma unroll 1
    for (int t = 0; t < NTILES; ++t) {
        __syncthreads();                  // consumers finished with smem
        *kdst = kreg;
        #pragma unroll
        for (int r = 0; r < 4; ++r) *(float4*)vdst[r] = vreg[r];

        const int tn = (t + 1 < NTILES) ? t + 1 : t;
        kreg = Ksrc[(size_t)tn * KT + kidx];
        #pragma unroll
        for (int r = 0; r < 4; ++r)
            vreg[r] = *(const float4*)(Vg + (size_t)vrow[r] * NN + tn * KT + vc16[r] * 8);
        __syncthreads();                  // tile visible

        // K b-fragments (8 n-tiles of 8 keys), hi and lo
        uint32_t kh[8], kl[8];
        LDSM4(kh[0], kh[1], kh[2], kh[3], aKhi);
        LDSM4(kh[4], kh[5], kh[6], kh[7], aKhi + 512);
        LDSM4(kl[0], kl[1], kl[2], kl[3], aKlo);
        LDSM4(kl[4], kl[5], kl[6], kl[7], aKlo + 512);

        // Scores: s = qhi.khi + qhi.klo + qlo.khi  (per 8-key n-tile)
        float p[8][4];
        #pragma unroll
        for (int nb = 0; nb < 8; ++nb) {
            MMA1688_Z(p[nb], qhi[0], qhi[1], kh[nb]);
            MMA1688(p[nb], qhi[0], qhi[1], kl[nb]);
            MMA1688(p[nb], qlo[0], qlo[1], kh[nb]);
        }
        // exp (log2e pre-folded): p = 2^s
        #pragma unroll
        for (int nb = 0; nb < 8; ++nb)
            #pragma unroll
            for (int e = 0; e < 4; ++e) p[nb][e] = ex2f(p[nb][e]);

        // P.V per 16-key k-tile
        #pragma unroll
        for (int kt = 0; kt < 4; ++kt) {
            const uint32_t a0 = packbf(p[2 * kt][0],     p[2 * kt][1]);
            const uint32_t a1 = packbf(p[2 * kt][2],     p[2 * kt][3]);
            const uint32_t a2 = packbf(p[2 * kt + 1][0], p[2 * kt + 1][1]);
            const uint32_t a3 = packbf(p[2 * kt + 1][2], p[2 * kt + 1][3]);

            uint32_t vb[16];
            #pragma unroll
            for (int c = 0; c < 4; ++c) {
                const uint32_t addr = vbase[c] + ((uint32_t)(((kt * 2 + m01) ^ vxor[c])) << 4);
                LDSM4(vb[4 * c + 0], vb[4 * c + 1], vb[4 * c + 2], vb[4 * c + 3], addr);
            }
            #pragma unroll
            for (int nb = 0; nb < 8; ++nb)
                MMA16816(acc[nb], a0, a1, a2, a3, vb[2 * nb], vb[2 * nb + 1]);
            MMA16816(lacc, a0, a1, a2, a3, ONES, ONES);   // row sums -> l
        }
    }

    // Output: lacc[0] = l(row g), lacc[2] = l(row g+8)
    const float invA = 1.f / lacc[0];
    const float invB = 1.f / lacc[2];
    float* outb = out + (size_t)b * CC * NN;
    const int rA = ibase + g;
    const int rB = rA + 8;
    #pragma unroll
    for (int nb = 0; nb < 8; ++nb) {
        const int c = nb * 8 + 2 * t4;
        outb[(size_t)c * NN + rA]       = acc[nb][0] * invA;
        outb[(size_t)(c + 1) * NN + rA] = acc[nb][1] * invA;
        outb[(size_t)c * NN + rB]       = acc[nb][2] * invB;
        outb[(size_t)(c + 1) * NN + rB] = acc[nb][3] * invB;
    }
}

// ---------------------------------------------------------------------------
extern "C" void kernel_launch(void* const* d_in, const int* in_sizes, int n_in,
                              void* d_out, int out_size)
{
    const float* x  = (const float*)d_in[0];
    const float* wq = (const float*)d_in[1];
    const float* bq = (const float*)d_in[2];
    const float* wk = (const float*)d_in[3];
    const float* bk = (const float*)d_in[4];
    const float* wv = (const float*)d_in[5];
    const float* bv = (const float*)d_in[6];
    float* out = (float*)d_out;

    dim3 pgrid(NN / 128, BB);
    proj_kernel<<<pgrid, 128>>>(x, wq, bq, wk, bk, wv, bv);

    dim3 agrid(NN / 64, BB);
    attn_kernel<<<agrid, 128>>>(out);
}

// round 6
// speedup vs baseline: 8.0758x; 1.1271x over previous
#include <cuda_runtime.h>
#include <cuda_bf16.h>
#include <cstdint>

#define BB 8
#define CC 64
#define CQ 8
#define NN 4096
#define KT 64
#define NTILES (NN / KT)
#define LOG2E 1.4426950408889634f

// Device scratch (allocation-free rule)
__device__ float g_Q[BB * NN * CQ];            // [b][n][cq] f32, pre-scaled by log2e
__device__ uint4 g_Khi[BB * NN];               // [b][n]: 8 bf16 (hi split)
__device__ uint4 g_Klo[BB * NN];               // [b][n]: 8 bf16 (lo split)
__device__ __nv_bfloat16 g_Vb[BB * CC * NN];   // [b][c][n] bf16 (V^T)

// ---------------------------------------------------------------------------
// PTX helpers (baseline compute_103-safe: sm_80-era instructions only)
// ---------------------------------------------------------------------------
__device__ __forceinline__ uint32_t smem_u32(const void* p) {
    uint32_t a;
    asm("{ .reg .u64 t; cvta.to.shared.u64 t, %1; cvt.u32.u64 %0, t; }" : "=r"(a) : "l"(p));
    return a;
}
__device__ __forceinline__ uint32_t packbf(float lo, float hi) {
    uint32_t r;
    asm("cvt.rn.bf16x2.f32 %0, %1, %2;" : "=r"(r) : "f"(hi), "f"(lo));
    return r;
}
__device__ __forceinline__ float ex2f(float x) {
    float y;
    asm("ex2.approx.f32 %0, %1;" : "=f"(y) : "f"(x));
    return y;
}
#define LDSM4(r0, r1, r2, r3, a) \
    asm volatile("ldmatrix.sync.aligned.m8n8.x4.shared.b16 {%0,%1,%2,%3}, [%4];" \
        : "=r"(r0), "=r"(r1), "=r"(r2), "=r"(r3) : "r"(a))

#define CP_ASYNC16(dst, src) \
    asm volatile("cp.async.ca.shared.global [%0], [%1], 16;" :: "r"(dst), "l"(src) : "memory")
#define CP_COMMIT() asm volatile("cp.async.commit_group;" ::: "memory")
#define CP_WAIT1()  asm volatile("cp.async.wait_group 1;" ::: "memory")

// m16n8k8 bf16 MMA, accumulate in place
#define MMA1688(d, a0, a1, b0) \
    asm volatile("mma.sync.aligned.m16n8k8.row.col.f32.bf16.bf16.f32 " \
        "{%0,%1,%2,%3}, {%4,%5}, {%6}, {%0,%1,%2,%3};" \
        : "+f"((d)[0]), "+f"((d)[1]), "+f"((d)[2]), "+f"((d)[3]) \
        : "r"(a0), "r"(a1), "r"(b0))
// m16n8k16 bf16 MMA, C = 0 (fresh)
#define MMA16816_Z(d, a0, a1, a2, a3, b0, b1) \
    asm volatile("mma.sync.aligned.m16n8k16.row.col.f32.bf16.bf16.f32 " \
        "{%0,%1,%2,%3}, {%4,%5,%6,%7}, {%8,%9}, {%10,%10,%10,%10};" \
        : "=f"((d)[0]), "=f"((d)[1]), "=f"((d)[2]), "=f"((d)[3]) \
        : "r"(a0), "r"(a1), "r"(a2), "r"(a3), "r"(b0), "r"(b1), "f"(0.f))
// m16n8k16 bf16 MMA, accumulate in place
#define MMA16816(d, a0, a1, a2, a3, b0, b1) \
    asm volatile("mma.sync.aligned.m16n8k16.row.col.f32.bf16.bf16.f32 " \
        "{%0,%1,%2,%3}, {%4,%5,%6,%7}, {%8,%9}, {%0,%1,%2,%3};" \
        : "+f"((d)[0]), "+f"((d)[1]), "+f"((d)[2]), "+f"((d)[3]) \
        : "r"(a0), "r"(a1), "r"(a2), "r"(a3), "r"(b0), "r"(b1))

// ---------------------------------------------------------------------------
// Kernel 1: 1x1-conv projections. 64-thr CTAs x 512 -> full-chip single wave.
//   Q f32 (scaled by log2e), K split into bf16 hi/lo, V^T bf16.
// wvT staged transposed with per-row rotation: row cin holds w[cout] at
// column (cout + 4*(cin&15)) & 63  -> 4-way STS conflicts (vs 32), float4-
// aligned uniform (broadcast) reads in the main loop.
// ---------------------------------------------------------------------------
__global__ void __launch_bounds__(64, 8) proj_kernel(
    const float* __restrict__ x,
    const float* __restrict__ wq, const float* __restrict__ bq,
    const float* __restrict__ wk, const float* __restrict__ bk,
    const float* __restrict__ wv, const float* __restrict__ bv)
{
    __shared__ float wvT[CC * 64];   // 16 KB (rotated layout)
    __shared__ float wqT[CC * CQ];   // [cin][cq]
    __shared__ float wkT[CC * CQ];
    __shared__ float s_bv[CC];
    __shared__ float s_bq[CQ];
    __shared__ float s_bk[CQ];

    const int tid = threadIdx.x;
    const int b   = blockIdx.y;
    const int n   = blockIdx.x * 64 + tid;

    // wv: coalesced LDG, rotated STS
    for (int idx = tid; idx < CC * CC; idx += 64) {
        const int cout = idx >> 6, cin = idx & 63;
        wvT[cin * 64 + ((cout + ((cin & 15) << 2)) & 63)] = wv[idx];
    }
    // wq/wk transposed to [cin][cq]
    for (int idx = tid; idx < CQ * CC; idx += 64) {
        const int cq = idx & 7, cin = idx >> 3;
        wqT[idx] = wq[cq * CC + cin];
        wkT[idx] = wk[cq * CC + cin];
    }
    if (tid < CC) s_bv[tid] = bv[tid];
    if (tid < CQ) { s_bq[tid] = bq[tid]; s_bk[tid] = bk[tid]; }
    __syncthreads();

    const float* xb = x + (size_t)b * CC * NN + n;

    float4 accv[16];
    float accq[CQ], acck[CQ];
    #pragma unroll
    for (int c4 = 0; c4 < 16; ++c4) {
        accv[c4].x = s_bv[c4 * 4 + 0];
        accv[c4].y = s_bv[c4 * 4 + 1];
        accv[c4].z = s_bv[c4 * 4 + 2];
        accv[c4].w = s_bv[c4 * 4 + 3];
    }
    #pragma unroll
    for (int cq = 0; cq < CQ; ++cq) { accq[cq] = s_bq[cq]; acck[cq] = s_bk[cq]; }

    #pragma unroll 4
    for (int cp = 0; cp < CC; ++cp) {
        const float xv = xb[(size_t)cp * NN];
        const float4* wrow = (const float4*)&wvT[cp * 64];
        const int rot = cp & 15;
        #pragma unroll
        for (int c4 = 0; c4 < 16; ++c4) {
            const float4 w = wrow[(c4 + rot) & 15];   // uniform broadcast
            accv[c4].x += w.x * xv;
            accv[c4].y += w.y * xv;
            accv[c4].z += w.z * xv;
            accv[c4].w += w.w * xv;
        }
        const float4 qw0 = ((const float4*)&wqT[cp * 8])[0];
        const float4 qw1 = ((const float4*)&wqT[cp * 8])[1];
        const float4 kw0 = ((const float4*)&wkT[cp * 8])[0];
        const float4 kw1 = ((const float4*)&wkT[cp * 8])[1];
        accq[0] += qw0.x * xv; accq[1] += qw0.y * xv;
        accq[2] += qw0.z * xv; accq[3] += qw0.w * xv;
        accq[4] += qw1.x * xv; accq[5] += qw1.y * xv;
        accq[6] += qw1.z * xv; accq[7] += qw1.w * xv;
        acck[0] += kw0.x * xv; acck[1] += kw0.y * xv;
        acck[2] += kw0.z * xv; acck[3] += kw0.w * xv;
        acck[4] += kw1.x * xv; acck[5] += kw1.y * xv;
        acck[6] += kw1.z * xv; acck[7] += kw1.w * xv;
    }

    // Q: f32 scaled by log2e
    float4* Qo = (float4*)(g_Q + ((size_t)b * NN + n) * CQ);
    Qo[0] = make_float4(accq[0] * LOG2E, accq[1] * LOG2E, accq[2] * LOG2E, accq[3] * LOG2E);
    Qo[1] = make_float4(accq[4] * LOG2E, accq[5] * LOG2E, accq[6] * LOG2E, accq[7] * LOG2E);

    // K: bf16 hi/lo split
    uint32_t hiw[4], low[4];
    #pragma unroll
    for (int p = 0; p < 4; ++p) {
        const float k0 = acck[2 * p], k1 = acck[2 * p + 1];
        const uint32_t h = packbf(k0, k1);
        const float h0 = __uint_as_float(h << 16);
        const float h1 = __uint_as_float(h & 0xFFFF0000u);
        hiw[p] = h;
        low[p] = packbf(k0 - h0, k1 - h1);
    }
    g_Khi[(size_t)b * NN + n] = make_uint4(hiw[0], hiw[1], hiw[2], hiw[3]);
    g_Klo[(size_t)b * NN + n] = make_uint4(low[0], low[1], low[2], low[3]);

    // V^T bf16
    __nv_bfloat16* Vo = g_Vb + (size_t)b * CC * NN + n;
    #pragma unroll
    for (int c4 = 0; c4 < 16; ++c4) {
        Vo[(size_t)(c4 * 4 + 0) * NN] = __float2bfloat16(accv[c4].x);
        Vo[(size_t)(c4 * 4 + 1) * NN] = __float2bfloat16(accv[c4].y);
        Vo[(size_t)(c4 * 4 + 2) * NN] = __float2bfloat16(accv[c4].z);
        Vo[(size_t)(c4 * 4 + 3) * NN] = __float2bfloat16(accv[c4].w);
    }
}

// ---------------------------------------------------------------------------
// Kernel 2: tensorized fused attention, 3-stage cp.async pipeline.
// Block = 128 thr = 4 warps x 16 query rows. grid (64, 8) = 512 CTAs, occ 4.
// smem stages (per stage: Khi 1KB | Klo 1KB | V 8KB), 3 stages = 30 KB.
// layout: [0) Khi s0..s2 (3KB) | [3072) Klo s0..s2 (3KB) | [6144) V s0..s2 (24KB)
// ---------------------------------------------------------------------------
__global__ void __launch_bounds__(128, 4) attn_kernel(float* __restrict__ out)
{
    __shared__ __align__(16) char smraw[6144 + 3 * 8192];

    const int tid  = threadIdx.x;
    const int lane = tid & 31;
    const int w    = tid >> 5;
    const int g    = lane >> 2;
    const int t4   = lane & 3;
    const int b    = blockIdx.y;
    const int ibase = blockIdx.x * 64 + w * 16;

    const uint32_t smb = smem_u32(smraw);

    // Q fragments (rows g, g+8; chans 2t4, 2t4+1), hi/lo bf16 split
    const float* Qb = g_Q + (size_t)b * NN * CQ;
    uint32_t qhi[2], qlo[2];
    #pragma unroll
    for (int r = 0; r < 2; ++r) {
        const float* qp = Qb + (size_t)(ibase + g + r * 8) * CQ + 2 * t4;
        const float q0 = qp[0], q1 = qp[1];
        const uint32_t h = packbf(q0, q1);
        qhi[r] = h;
        qlo[r] = packbf(q0 - __uint_as_float(h << 16),
                        q1 - __uint_as_float(h & 0xFFFF0000u));
    }

    // K staging: threads 0-63 copy hi, 64-127 copy lo (one 16B copy each/tile)
    const uint4* Ksrc = ((tid < 64) ? g_Khi : g_Klo) + (size_t)b * NN + (tid & 63);
    const uint32_t kdst = smb + ((tid < 64) ? 0u : 3072u) + (uint32_t)(tid & 63) * 16u;

    // V staging: 4 x 16B copies per thread per tile, xor-swizzled rows
    const char* Vgb = (const char*)(g_Vb + (size_t)b * CC * NN);
    uint32_t voff[4], vdst[4];
    #pragma unroll
    for (int r = 0; r < 4; ++r) {
        const int idx = r * 128 + tid;
        const int vrow = idx >> 3, vc16 = idx & 7;
        voff[r] = (uint32_t)vrow * (NN * 2) + vc16 * 16;
        vdst[r] = smb + 6144 + vrow * 128 + (uint32_t)((vc16 ^ (vrow & 7)) << 4);
    }

    // ldmatrix addresses
    const uint32_t aKhi = smb + lane * 16;
    const uint32_t aKlo = smb + 3072 + lane * 16;
    const int mat = lane >> 3, mrow = lane & 7, m01 = mat & 1;
    uint32_t vbase[4];
    int vxor[4];
    #pragma unroll
    for (int c = 0; c < 4; ++c) {
        const int row = (2 * c + (mat >> 1)) * 8 + mrow;
        vbase[c] = smb + 6144 + row * 128;
        vxor[c]  = row & 7;
    }

    // Prologue: async-copy tiles 0 and 1 into stages 0, 1
    #pragma unroll
    for (int t = 0; t < 2; ++t) {
        CP_ASYNC16(kdst + t * 1024, Ksrc + (size_t)t * KT);
        #pragma unroll
        for (int r = 0; r < 4; ++r)
            CP_ASYNC16(vdst[r] + t * 8192, Vgb + voff[r] + t * 128);
        CP_COMMIT();
    }

    float acc[8][4];
    #pragma unroll
    for (int nb = 0; nb < 8; ++nb)
        #pragma unroll
        for (int e = 0; e < 4; ++e) acc[nb][e] = 0.f;
    float lsum0 = 0.f, lsum1 = 0.f;
    uint32_t ksoff = 0, vsoff = 0;

    #pragma unroll 1
    for (int t = 0; t < NTILES; ++t) {
        CP_WAIT1();             // tile t's copies complete
        __syncthreads();        // ...in every thread; stage t-1 fully consumed

        // Issue copies for tile t+2 into stage (t+2)%3 (== stage of t-1)
        {
            const int tc = t + 2;
            uint32_t ks2 = ksoff + 2048; if (ks2 >= 3072)  ks2 -= 3072;
            uint32_t vs2 = vsoff + 16384; if (vs2 >= 24576) vs2 -= 24576;
            if (tc < NTILES) {
                CP_ASYNC16(kdst + ks2, Ksrc + (size_t)tc * KT);
                #pragma unroll
                for (int r = 0; r < 4; ++r)
                    CP_ASYNC16(vdst[r] + vs2, Vgb + voff[r] + (size_t)tc * 128);
            }
            CP_COMMIT();        // always commit (possibly empty) to keep counts
        }

        // K b-fragments for this tile (8 n-tiles of 8 keys), hi and lo
        uint32_t kh[8], kl[8];
        LDSM4(kh[0], kh[1], kh[2], kh[3], aKhi + ksoff);
        LDSM4(kh[4], kh[5], kh[6], kh[7], aKhi + ksoff + 512);
        LDSM4(kl[0], kl[1], kl[2], kl[3], aKlo + ksoff);
        LDSM4(kl[4], kl[5], kl[6], kl[7], aKlo + ksoff + 512);

        #pragma unroll
        for (int kt = 0; kt < 4; ++kt) {
            // scores: (qhi+qlo).khi via one k16, + qhi.klo via one k8
            float p0[4], p1[4];
            MMA16816_Z(p0, qhi[0], qhi[1], qlo[0], qlo[1], kh[2 * kt], kh[2 * kt]);
            MMA1688(p0, qhi[0], qhi[1], kl[2 * kt]);
            MMA16816_Z(p1, qhi[0], qhi[1], qlo[0], qlo[1], kh[2 * kt + 1], kh[2 * kt + 1]);
            MMA1688(p1, qhi[0], qhi[1], kl[2 * kt + 1]);

            #pragma unroll
            for (int e = 0; e < 4; ++e) { p0[e] = ex2f(p0[e]); p1[e] = ex2f(p1[e]); }
            lsum0 += (p0[0] + p0[1]) + (p1[0] + p1[1]);
            lsum1 += (p0[2] + p0[3]) + (p1[2] + p1[3]);

            const uint32_t a0 = packbf(p0[0], p0[1]);
            const uint32_t a1 = packbf(p0[2], p0[3]);
            const uint32_t a2 = packbf(p1[0], p1[1]);
            const uint32_t a3 = packbf(p1[2], p1[3]);

            uint32_t vb[16];
            #pragma unroll
            for (int c = 0; c < 4; ++c) {
                const uint32_t addr = vbase[c] + vsoff
                    + ((uint32_t)(((kt * 2 + m01) ^ vxor[c])) << 4);
                LDSM4(vb[4 * c + 0], vb[4 * c + 1], vb[4 * c + 2], vb[4 * c + 3], addr);
            }
            #pragma unroll
            for (int nb = 0; nb < 8; ++nb)
                MMA16816(acc[nb], a0, a1, a2, a3, vb[2 * nb], vb[2 * nb + 1]);
        }

        ksoff += 1024; if (ksoff == 3072)  ksoff = 0;
        vsoff += 8192; if (vsoff == 24576) vsoff = 0;
    }

    // l: reduce over the 4 lanes of each quad (keys split across t4)
    lsum0 += __shfl_xor_sync(0xFFFFFFFFu, lsum0, 1);
    lsum0 += __shfl_xor_sync(0xFFFFFFFFu, lsum0, 2);
    lsum1 += __shfl_xor_sync(0xFFFFFFFFu, lsum1, 1);
    lsum1 += __shfl_xor_sync(0xFFFFFFFFu, lsum1, 2);
    const float invA = 1.f / lsum0;
    const float invB = 1.f / lsum1;

    float* outb = out + (size_t)b * CC * NN;
    const int rA = ibase + g;
    const int rB = rA + 8;
    #pragma unroll
    for (int nb = 0; nb < 8; ++nb) {
        const int c = nb * 8 + 2 * t4;
        outb[(size_t)c * NN + rA]       = acc[nb][0] * invA;
        outb[(size_t)(c + 1) * NN + rA] = acc[nb][1] * invA;
        outb[(size_t)c * NN + rB]       = acc[nb][2] * invB;
        outb[(size_t)(c + 1) * NN + rB] = acc[nb][3] * invB;
    }
}

// ---------------------------------------------------------------------------
extern "C" void kernel_launch(void* const* d_in, const int* in_sizes, int n_in,
                              void* d_out, int out_size)
{
    const float* x  = (const float*)d_in[0];
    const float* wq = (const float*)d_in[1];
    const float* bq = (const float*)d_in[2];
    const float* wk = (const float*)d_in[3];
    const float* bk = (const float*)d_in[4];
    const float* wv = (const float*)d_in[5];
    const float* bv = (const float*)d_in[6];
    float* out = (float*)d_out;

    dim3 pgrid(NN / 64, BB);
    proj_kernel<<<pgrid, 64>>>(x, wq, bq, wk, bk, wv, bv);

    dim3 agrid(NN / 64, BB);
    attn_kernel<<<agrid, 128>>>(out);
}